// round 10
// baseline (speedup 1.0000x reference)
#include <cuda_runtime.h>
#include <cuda_bf16.h>

// Problem constants
#define NXS    41
#define GTOT   68921          // 41^3
#define NX2    1681           // 41^2
#define WPAD2  2160           // padded word count (covers shifts, tail zero)
#define CHUNKS 539            // chunk = 128 voxels (4 mask words)
#define KPK    4
#define NEGV   (-1.0e9f)
#define VTH    (-1.0e8f)
#define NPAIR  512            // B*N*C = 1*128*4
#define FULLM  0xffffffffu

// Compile-time axis coords: float((i-20)*0.3 computed in double) — bit-exact vs numpy
struct AxTable { float v[NXS]; };
static constexpr AxTable make_ax()
{
    AxTable t{};
    for (int i = 0; i < NXS; ++i) t.v[i] = (float)((double)(i - 20) * 0.3);
    return t;
}
__constant__ AxTable c_ax = make_ax();

// Shifted sphere masks: S_a bit p <-> voxel g = p + a. Tail words zero.
__device__ unsigned int g_S[4][WPAD2];
__device__ int g_list[4][CHUNKS];   // non-empty chunk ids per variant
__device__ int g_nlist[4];
__device__ unsigned int g_ckey[NPAIR][544];   // per-pair unmasked chunk maxima

// ---------------------------------------------------------------------------
// Kernel 1: dense sphere mask (variant 0 only), axis table staged via shared
// ---------------------------------------------------------------------------
__global__ __launch_bounds__(256) void init_masks_kernel()
{
    __shared__ float ax[NXS];
    if (threadIdx.x < NXS) ax[threadIdx.x] = c_ax.v[threadIdx.x];
    __syncthreads();
    int g = blockIdx.x * 256 + threadIdx.x;    // dense bit position (0..69119)
    bool ok = false;
    if (g < GTOT) {
        int i = g / NX2;
        int j = (g / NXS) % NXS;
        int k = g % NXS;
        float x = ax[i], y = ax[j], z = ax[k];
        float s = __fadd_rn(__fadd_rn(__fmul_rn(x, x), __fmul_rn(y, y)), __fmul_rn(z, z));
        ok = (__fsqrt_rn(s) <= 6.0f);
    }
    unsigned int ballot = __ballot_sync(FULLM, ok);
    if ((threadIdx.x & 31) == 0) {
        int w = g >> 5;
        if (w < WPAD2) g_S[0][w] = ballot;     // bits >= GTOT are 0 by construction
    }
}

// ---------------------------------------------------------------------------
// Kernel 2: derive shifted masks via funnel shift + build non-empty chunk lists
// ---------------------------------------------------------------------------
__global__ __launch_bounds__(128) void build_lists_kernel()
{
    for (int w = threadIdx.x; w < WPAD2; w += 128) {
        unsigned int lo = g_S[0][w];
        unsigned int hi = (w + 1 < WPAD2) ? g_S[0][w + 1] : 0u;
        g_S[1][w] = __funnelshift_r(lo, hi, 1);
        g_S[2][w] = __funnelshift_r(lo, hi, 2);
        g_S[3][w] = __funnelshift_r(lo, hi, 3);
    }
    __syncthreads();
    int a = threadIdx.x >> 5;
    int lane = threadIdx.x & 31;
    const unsigned int* S = g_S[a];
    int count = 0;
    for (int base = 0; base < CHUNKS; base += 32) {
        int c = base + lane;
        bool ne = false;
        if (c < CHUNKS)
            ne = (S[c * 4] | S[c * 4 + 1] | S[c * 4 + 2] | S[c * 4 + 3]) != 0u;
        unsigned int bal = __ballot_sync(FULLM, ne);
        int pos = count + __popc(bal & ((1u << lane) - 1u));
        if (ne) g_list[a][pos] = c;
        count += __popc(bal);
    }
    if (lane == 0) g_nlist[a] = count;
}

// order-preserving float->uint key; 0 = "masked" (below all real keys)
__device__ __forceinline__ unsigned int f2key(float v)
{
    int i = __float_as_int(v);
    return (unsigned int)(i ^ ((i >> 31) | 0x80000000));
}
__device__ __forceinline__ float key2f(unsigned int k)
{
    int i = (k & 0x80000000u) ? (int)(k ^ 0x80000000u) : (int)~k;
    return __int_as_float(i);
}
__device__ __forceinline__ unsigned int sext_bit(unsigned int w, int bitpos)
{
    return (unsigned int)(((int)(w << (31 - bitpos))) >> 31);
}

// ---------------------------------------------------------------------------
// Kernel 3: streaming UNMASKED float4 chunk-max scan. 4 CTAs per pair.
// ---------------------------------------------------------------------------
__global__ __launch_bounds__(256) void scan_kernel(const float* __restrict__ density)
{
    __shared__ int slist[CHUNKS];
    const int part = blockIdx.x & 3;
    const int pair = blockIdx.x >> 2;
    const int aoff = (-pair) & 3;
    const int nl   = g_nlist[aoff];
    const float4* __restrict__ dens4 =
        (const float4*)(density + (size_t)pair * GTOT + aoff);
    const int lane = threadIdx.x & 31;
    const int wid  = threadIdx.x >> 5;

    for (int e = threadIdx.x; e < nl; e += 256) slist[e] = g_list[aoff][e];
    __syncthreads();

    const int q  = (nl + 3) >> 2;
    const int s0 = part * q;
    const int s1 = min(s0 + q, nl);
    unsigned int* __restrict__ ck = g_ckey[pair];

    for (int e0 = s0 + wid * 4; e0 < s1; e0 += 32) {
        int    cc[4];
        float4 ff[4];
        #pragma unroll
        for (int b = 0; b < 4; ++b) {
            int e = min(e0 + b, s1 - 1);          // dup-clamped tail
            cc[b] = slist[e];
            ff[b] = __ldg(dens4 + cc[b] * 32 + lane);
        }
        #pragma unroll
        for (int b = 0; b < 4; ++b) {
            float m = fmaxf(fmaxf(ff[b].x, ff[b].y), fmaxf(ff[b].z, ff[b].w));
            unsigned int r = __reduce_max_sync(FULLM, f2key(m));
            if (lane == 0 && e0 + b < s1) ck[cc[b]] = r;
        }
    }
}

// ---------------------------------------------------------------------------
// Kernel 4: per-(n,c) verified argmax + Chebyshev NMS (lazy stale upper bounds)
// ---------------------------------------------------------------------------
__global__ __launch_bounds__(256) void pick_kernel(
    const float* __restrict__ density,   // [512, G]
    const float* __restrict__ grid_xyz,  // [G, 3]
    const float* __restrict__ Rmats,     // [128, 3, 3]
    const float* __restrict__ tpos,      // [128, 3]
    const float* __restrict__ node_mask, // [128]
    float* __restrict__ out)             // 16384 floats
{
    __shared__ unsigned int smask[WPAD2];   // live shifted bits
    __shared__ unsigned int ckey[CHUNKS];   // upper-bound chunk maxima
    __shared__ unsigned int swk[8];
    __shared__ int          sww[8];
    __shared__ float pk_score[KPK];
    __shared__ int   pk_idx[KPK];
    __shared__ int   pk_valid[KPK];
    __shared__ int   cur_i, cur_j, cur_k, cur_valid, s_done;

    const int pair = blockIdx.x;            // n*4 + c
    const int tid  = threadIdx.x;
    const int lane = tid & 31;
    const int wid  = tid >> 5;
    const int aoff = (-pair) & 3;           // alignment shift (voxels)
    const float4* __restrict__ dens4 =
        (const float4*)(density + (size_t)pair * GTOT + aoff);
    const unsigned int* __restrict__ S = g_S[aoff];
    const int* __restrict__ list = g_list[aoff];
    const int nl = g_nlist[aoff];

    for (int w = tid; w < WPAD2; w += 256) smask[w] = S[w];
    for (int c = tid; c < CHUNKS; c += 256) ckey[c] = 0u;
    __syncthreads();
    for (int e = tid; e < nl; e += 256) {
        int c = __ldg(&list[e]);
        ckey[c] = __ldg(&g_ckey[pair][c]);
    }
    __syncthreads();

    for (int t = 0; t < KPK; ++t) {
        // ---- verified argmax loop (ckey entries are upper bounds) ----
        for (;;) {
            unsigned int bk = 0;
            int bc = 0x7FFFFFFF;
            for (int c = tid; c < CHUNKS; c += 256) {
                unsigned int k = ckey[c];
                if (k > bk) { bk = k; bc = c; }   // ascending: lowest c on ties
            }
            unsigned int wm = __reduce_max_sync(FULLM, bk);
            int cand = (bk == wm) ? bc : 0x7FFFFFFF;
            int wmin = (int)__reduce_min_sync(FULLM, (unsigned int)cand);
            if (lane == 0) { swk[wid] = wm; sww[wid] = wmin; }
            __syncthreads();
            if (wid == 0) {
                unsigned int k8 = (lane < 8) ? swk[lane] : 0u;
                int w8 = (lane < 8) ? sww[lane] : 0x7FFFFFFF;
                unsigned int fm = __reduce_max_sync(FULLM, k8);
                int c8 = (k8 == fm) ? w8 : 0x7FFFFFFF;
                int fc = (int)__reduce_min_sync(FULLM, (unsigned int)c8);
                // masked verification of chunk fc
                float4 f = __ldg(dens4 + fc * 32 + lane);
                unsigned int mw = smask[fc * 4 + (lane >> 3)];
                int sh = (lane & 7) * 4;
                unsigned int k0 = f2key(f.x) & sext_bit(mw, sh + 0);
                unsigned int k1 = f2key(f.y) & sext_bit(mw, sh + 1);
                unsigned int k2 = f2key(f.z) & sext_bit(mw, sh + 2);
                unsigned int k3 = f2key(f.w) & sext_bit(mw, sh + 3);
                unsigned int bestk = k0; int besti = 0;
                if (k1 > bestk) { bestk = k1; besti = 1; }
                if (k2 > bestk) { bestk = k2; besti = 2; }
                if (k3 > bestk) { bestk = k3; besti = 3; }
                unsigned int mk = __reduce_max_sync(FULLM, bestk);
                if (mk == fm) {
                    // accept: lowest-g argmax within chunk
                    int gl = fc * 128 + lane * 4 + besti;
                    int cg = (bestk == mk) ? gl : 0x7FFFFFFF;
                    int gp = (int)__reduce_min_sync(FULLM, (unsigned int)cg);
                    if (lane == 0) {
                        int gi = gp + aoff;          // absolute voxel index
                        float sc = key2f(fm);
                        int valid = (sc > VTH) ? 1 : 0;
                        pk_score[t] = sc;
                        pk_idx[t]   = gi;
                        pk_valid[t] = valid;
                        cur_valid = valid;
                        cur_i = gi / NX2;
                        cur_j = (gi / NXS) % NXS;
                        cur_k = gi % NXS;
                        s_done = 1;
                    }
                } else {
                    // stale upper bound: decrease-key and retry
                    if (lane == 0) { ckey[fc] = mk; s_done = 0; }
                }
            }
            __syncthreads();
            if (s_done) break;
        }

        if (t < KPK - 1 && cur_valid) {
            // ---- clear bits in <=7x7x7 Chebyshev cube (shifted coords).
            //      ckey stays a valid upper bound; pops self-correct. ----
            int i0 = max(cur_i - 3, 0), i1 = min(cur_i + 3, NXS - 1);
            int j0 = max(cur_j - 3, 0), j1 = min(cur_j + 3, NXS - 1);
            int k0c = max(cur_k - 3, 0), k1c = min(cur_k + 3, NXS - 1);
            int nj = j1 - j0 + 1;
            int nrows = (i1 - i0 + 1) * nj;
            // rows >=35 bits apart -> never share a 32-bit word -> no races
            if (tid < nrows) {
                int i = i0 + tid / nj;
                int j = j0 + tid % nj;
                int pb = i * NX2 + j * NXS + k0c - aoff;   // shifted position
                int pe = pb + (k1c - k0c);
                int w0 = pb >> 5, w1 = pe >> 5;
                unsigned int b0 = (unsigned int)(pb & 31);
                unsigned int b1 = (unsigned int)(pe & 31);
                unsigned int hi = (b1 == 31u) ? FULLM : ((1u << (b1 + 1)) - 1u);
                if (w0 == w1) {
                    unsigned int msk = hi & ~((1u << b0) - 1u);
                    smask[w0] &= ~msk;
                } else {
                    smask[w0] &= ((1u << b0) - 1u);
                    smask[w1] &= ~hi;
                }
            }
        }
        __syncthreads();
    }

    // ---- outputs ----
    // layout: coords_local[6144] | coords_global[6144] | scores[2048] | mask[2048]
    if (tid < KPK) {
        int k = tid;
        int n = pair >> 2;
        float nm = node_mask[n];
        int valid = pk_valid[k];
        float sc = valid ? pk_score[k] : NEGV;
        float x = 0.0f, y = 0.0f, z = 0.0f;
        if (valid) {
            int gi = pk_idx[k];
            x = grid_xyz[3 * gi + 0];
            y = grid_xyz[3 * gi + 1];
            z = grid_xyz[3 * gi + 2];
        }
        int o = (pair * KPK + k) * 3;
        out[o + 0] = x * nm;
        out[o + 1] = y * nm;
        out[o + 2] = z * nm;
        const float* R  = Rmats + n * 9;
        const float* tp = tpos + n * 3;
        float gx = R[0] * x + R[1] * y + R[2] * z + tp[0];
        float gy = R[3] * x + R[4] * y + R[5] * z + tp[1];
        float gz = R[6] * x + R[7] * y + R[8] * z + tp[2];
        out[6144 + o + 0] = gx * nm;
        out[6144 + o + 1] = gy * nm;
        out[6144 + o + 2] = gz * nm;
        out[12288 + pair * KPK + k] = sc * nm;
        out[14336 + pair * KPK + k] = (valid && nm != 0.0f) ? 1.0f : 0.0f;
    }
}

extern "C" void kernel_launch(void* const* d_in, const int* in_sizes, int n_in,
                              void* d_out, int out_size)
{
    // metadata order: density, grid_xyz, sphere_mask, coords_int, Rmats, tpos, node_mask
    const float* density   = (const float*)d_in[0];
    const float* grid_xyz  = (const float*)d_in[1];
    const float* Rmats     = (const float*)d_in[4];
    const float* tpos      = (const float*)d_in[5];
    const float* node_mask = (const float*)d_in[6];
    float* out = (float*)d_out;

    init_masks_kernel<<<270, 256>>>();      // dense mask (2160 words)
    build_lists_kernel<<<1, 128>>>();       // shifted masks + chunk lists
    scan_kernel<<<NPAIR * 4, 256>>>(density);
    pick_kernel<<<NPAIR, 256>>>(density, grid_xyz, Rmats, tpos, node_mask, out);
}

// round 11
// speedup vs baseline: 1.3944x; 1.3944x over previous
#include <cuda_runtime.h>
#include <cuda_bf16.h>

// Problem constants
#define NXS    41
#define GTOT   68921          // 41^3
#define NX2    1681           // 41^2
#define NWORDS 2160           // dense mask words (tail zero)
#define CHUNKS 539            // chunk = 128 voxels (4 mask words)
#define KPK    4
#define NEGV   (-1.0e9f)
#define VTH    (-1.0e8f)
#define NPAIR  512            // B*N*C = 1*128*4
#define FULLM  0xffffffffu

// Compile-time axis coords: float((i-20)*0.3 computed in double) — bit-exact vs numpy
struct AxTable { float v[NXS]; };
static constexpr AxTable make_ax()
{
    AxTable t{};
    for (int i = 0; i < NXS; ++i) t.v[i] = (float)((double)(i - 20) * 0.3);
    return t;
}
__constant__ AxTable c_ax = make_ax();

// Compile-time conservative non-empty chunk lists per alignment shift a (0..3):
// chunk c listed iff any voxel g = c*128+p+a (p<128, g<GTOT) has r^2 <= 36.01 (double).
// Superset of the true in-sphere chunks -> safe (bounds are verified upper bounds).
struct ChunkLists { short list[4][CHUNKS]; int n[4]; };
static constexpr ChunkLists make_lists()
{
    ChunkLists L{};
    for (int a = 0; a < 4; ++a) {
        int cnt = 0;
        for (int c = 0; c < CHUNKS; ++c) {
            bool ne = false;
            for (int p = c * 128; p < c * 128 + 128 && !ne; ++p) {
                int g = p + a;
                if (g >= GTOT) break;
                int i = g / NX2, j = (g / NXS) % NXS, kk = g % NXS;
                double x = (i - 20) * 0.3, y = (j - 20) * 0.3, z = (kk - 20) * 0.3;
                if (x * x + y * y + z * z <= 36.01) ne = true;
            }
            if (ne) { L.list[a][cnt] = (short)c; ++cnt; }
        }
        L.n[a] = cnt;
    }
    return L;
}
__constant__ ChunkLists c_lists = make_lists();

// Dense sphere mask (exact fp32 semantics), tail words zero
__device__ unsigned int g_S0[NWORDS];

// ---------------------------------------------------------------------------
// Kernel 1: dense sphere mask, numpy-identical fp32 op sequence
// ---------------------------------------------------------------------------
__global__ __launch_bounds__(256) void init_masks_kernel()
{
    __shared__ float ax[NXS];
    if (threadIdx.x < NXS) ax[threadIdx.x] = c_ax.v[threadIdx.x];
    __syncthreads();
    int g = blockIdx.x * 256 + threadIdx.x;    // 270*256 = 69120 = 2160 words
    bool ok = false;
    if (g < GTOT) {
        int i = g / NX2;
        int j = (g / NXS) % NXS;
        int k = g % NXS;
        float x = ax[i], y = ax[j], z = ax[k];
        float s = __fadd_rn(__fadd_rn(__fmul_rn(x, x), __fmul_rn(y, y)), __fmul_rn(z, z));
        ok = (__fsqrt_rn(s) <= 6.0f);
    }
    unsigned int ballot = __ballot_sync(FULLM, ok);
    if ((threadIdx.x & 31) == 0) g_S0[g >> 5] = ballot;
}

// order-preserving float->uint key; 0 = "masked" (below all real keys)
__device__ __forceinline__ unsigned int f2key(float v)
{
    int i = __float_as_int(v);
    return (unsigned int)(i ^ ((i >> 31) | 0x80000000));
}
__device__ __forceinline__ float key2f(unsigned int k)
{
    int i = (k & 0x80000000u) ? (int)(k ^ 0x80000000u) : (int)~k;
    return __int_as_float(i);
}
__device__ __forceinline__ unsigned int sext_bit(unsigned int w, int bitpos)
{
    return (unsigned int)(((int)(w << (31 - bitpos))) >> 31);
}

// ---------------------------------------------------------------------------
// Kernel 2 (fused): 8-warp unmasked float4 chunk scan, then warp-0-only
// verified argmax + lazy Chebyshev NMS (warp-synchronous, no block barriers).
// ---------------------------------------------------------------------------
__global__ __launch_bounds__(256) void peaks_kernel(
    const float* __restrict__ density,   // [512, G]
    const float* __restrict__ grid_xyz,  // [G, 3]
    const float* __restrict__ Rmats,     // [128, 3, 3]
    const float* __restrict__ tpos,      // [128, 3]
    const float* __restrict__ node_mask, // [128]
    float* __restrict__ out)             // 16384 floats
{
    __shared__ unsigned int smask[NWORDS];  // live shifted bits
    __shared__ unsigned int ckey[CHUNKS];   // upper-bound chunk maxima
    __shared__ int          slist[CHUNKS];

    const int pair = blockIdx.x;            // n*4 + c
    const int tid  = threadIdx.x;
    const int lane = tid & 31;
    const int wid  = tid >> 5;
    const int aoff = (-pair) & 3;           // alignment shift (voxels)
    const float4* __restrict__ dens4 =
        (const float4*)(density + (size_t)pair * GTOT + aoff);
    const int nl = c_lists.n[aoff];

    // shifted mask on the fly: S_a[w] = (S0 >> a) across word boundary
    for (int w = tid; w < NWORDS; w += 256) {
        unsigned int lo = g_S0[w];
        unsigned int hi = (w + 1 < NWORDS) ? g_S0[w + 1] : 0u;
        smask[w] = __funnelshift_r(lo, hi, aoff);
    }
    for (int c = tid; c < CHUNKS; c += 256) ckey[c] = 0u;
    for (int e = tid; e < nl; e += 256) slist[e] = c_lists.list[aoff][e];
    __syncthreads();

    // ---- phase A: unmasked per-chunk max over listed chunks (8 warps) ----
    for (int e0 = wid * 4; e0 < nl; e0 += 32) {
        int    cc[4];
        float4 ff[4];
        #pragma unroll
        for (int b = 0; b < 4; ++b) {
            int e = min(e0 + b, nl - 1);          // dup-clamped tail
            cc[b] = slist[e];
            ff[b] = __ldg(dens4 + cc[b] * 32 + lane);
        }
        #pragma unroll
        for (int b = 0; b < 4; ++b) {
            float m = fmaxf(fmaxf(ff[b].x, ff[b].y), fmaxf(ff[b].z, ff[b].w));
            unsigned int r = __reduce_max_sync(FULLM, f2key(m));
            if (lane == 0 && e0 + b < nl) ckey[cc[b]] = r;
        }
    }
    __syncthreads();

    if (wid != 0) return;   // warps 1-7 done; no further block barriers

    // ---- phase B: warp-synchronous verified argmax + lazy NMS ----
    float pk_score[KPK];
    int   pk_idx[KPK];
    int   pk_valid[KPK];

    for (int t = 0; t < KPK; ++t) {
        int gi = 0, valid = 0;
        float sc = 0.0f;
        for (;;) {
            // argmax over upper bounds (lowest chunk on ties)
            unsigned int bk = 0;
            int bc = 0x7FFFFFFF;
            for (int c = lane; c < CHUNKS; c += 32) {
                unsigned int k = ckey[c];
                if (k > bk) { bk = k; bc = c; }   // ascending: lowest c per lane
            }
            unsigned int fm = __reduce_max_sync(FULLM, bk);
            int cand = (bk == fm) ? bc : 0x7FFFFFFF;
            int fc = (int)__reduce_min_sync(FULLM, (unsigned int)cand);
            // masked verification of chunk fc
            float4 f = __ldg(dens4 + fc * 32 + lane);
            unsigned int mw = smask[fc * 4 + (lane >> 3)];
            int sh = (lane & 7) * 4;
            unsigned int k0 = f2key(f.x) & sext_bit(mw, sh + 0);
            unsigned int k1 = f2key(f.y) & sext_bit(mw, sh + 1);
            unsigned int k2 = f2key(f.z) & sext_bit(mw, sh + 2);
            unsigned int k3 = f2key(f.w) & sext_bit(mw, sh + 3);
            unsigned int bestk = k0; int besti = 0;
            if (k1 > bestk) { bestk = k1; besti = 1; }
            if (k2 > bestk) { bestk = k2; besti = 2; }
            if (k3 > bestk) { bestk = k3; besti = 3; }
            unsigned int mk = __reduce_max_sync(FULLM, bestk);
            if (mk == fm) {
                // accept: lowest-g argmax within chunk
                int gl = fc * 128 + lane * 4 + besti;
                int cg = (bestk == mk) ? gl : 0x7FFFFFFF;
                int gp = (int)__reduce_min_sync(FULLM, (unsigned int)cg);
                gi = gp + aoff;                  // absolute voxel index
                sc = key2f(fm);
                valid = (sc > VTH) ? 1 : 0;
                break;
            }
            // stale upper bound: decrease-key and retry
            if (lane == 0) ckey[fc] = mk;
            __syncwarp();
        }
        pk_score[t] = sc;
        pk_idx[t]   = gi;
        pk_valid[t] = valid;

        if (t < KPK - 1 && valid) {
            // clear bits in <=7x7x7 Chebyshev cube (shifted coords);
            // ckey stays a valid upper bound; pops self-correct.
            int ci = gi / NX2, cj = (gi / NXS) % NXS, ck = gi % NXS;
            int i0 = max(ci - 3, 0), i1 = min(ci + 3, NXS - 1);
            int j0 = max(cj - 3, 0), j1 = min(cj + 3, NXS - 1);
            int k0c = max(ck - 3, 0), k1c = min(ck + 3, NXS - 1);
            int nj = j1 - j0 + 1;
            int nrows = (i1 - i0 + 1) * nj;
            // rows >=41 bits apart -> never share a 32-bit word -> race-free
            for (int r = lane; r < nrows; r += 32) {
                int i = i0 + r / nj;
                int j = j0 + r % nj;
                int pb = i * NX2 + j * NXS + k0c - aoff;   // shifted position
                int pe = pb + (k1c - k0c);
                int w0 = pb >> 5, w1 = pe >> 5;
                unsigned int b0 = (unsigned int)(pb & 31);
                unsigned int b1 = (unsigned int)(pe & 31);
                unsigned int hi = (b1 == 31u) ? FULLM : ((1u << (b1 + 1)) - 1u);
                if (w0 == w1) {
                    unsigned int msk = hi & ~((1u << b0) - 1u);
                    smask[w0] &= ~msk;
                } else {
                    smask[w0] &= ((1u << b0) - 1u);
                    smask[w1] &= ~hi;
                }
            }
            __syncwarp();
        }
    }

    // ---- outputs (warp 0, lanes 0-3) ----
    // layout: coords_local[6144] | coords_global[6144] | scores[2048] | mask[2048]
    if (lane < KPK) {
        int k = lane;
        int n = pair >> 2;
        float nm = node_mask[n];
        int valid = pk_valid[k];
        float sc = valid ? pk_score[k] : NEGV;
        float x = 0.0f, y = 0.0f, z = 0.0f;
        if (valid) {
            int gi = pk_idx[k];
            x = grid_xyz[3 * gi + 0];
            y = grid_xyz[3 * gi + 1];
            z = grid_xyz[3 * gi + 2];
        }
        int o = (pair * KPK + k) * 3;
        out[o + 0] = x * nm;
        out[o + 1] = y * nm;
        out[o + 2] = z * nm;
        const float* R  = Rmats + n * 9;
        const float* tp = tpos + n * 3;
        float gx = R[0] * x + R[1] * y + R[2] * z + tp[0];
        float gy = R[3] * x + R[4] * y + R[5] * z + tp[1];
        float gz = R[6] * x + R[7] * y + R[8] * z + tp[2];
        out[6144 + o + 0] = gx * nm;
        out[6144 + o + 1] = gy * nm;
        out[6144 + o + 2] = gz * nm;
        out[12288 + pair * KPK + k] = sc * nm;
        out[14336 + pair * KPK + k] = (valid && nm != 0.0f) ? 1.0f : 0.0f;
    }
}

extern "C" void kernel_launch(void* const* d_in, const int* in_sizes, int n_in,
                              void* d_out, int out_size)
{
    // metadata order: density, grid_xyz, sphere_mask, coords_int, Rmats, tpos, node_mask
    const float* density   = (const float*)d_in[0];
    const float* grid_xyz  = (const float*)d_in[1];
    const float* Rmats     = (const float*)d_in[4];
    const float* tpos      = (const float*)d_in[5];
    const float* node_mask = (const float*)d_in[6];
    float* out = (float*)d_out;

    init_masks_kernel<<<270, 256>>>();
    peaks_kernel<<<NPAIR, 256>>>(density, grid_xyz, Rmats, tpos, node_mask, out);
}

// round 12
// speedup vs baseline: 1.4923x; 1.0702x over previous
#include <cuda_runtime.h>
#include <cuda_bf16.h>

// Problem constants
#define NXS    41
#define GTOT   68921          // 41^3
#define NX2    1681           // 41^2
#define NWORDS 2160           // dense mask words (tail zero)
#define CHUNKS 539            // chunk = 128 voxels (4 mask words)
#define KPK    4
#define NEGV   (-1.0e9f)
#define VTH    (-1.0e8f)
#define NPAIR  512            // B*N*C = 1*128*4
#define FULLM  0xffffffffu
#define NTHR   384            // 12 warps
#define NWARP  12

// Compile-time axis coords: float((i-20)*0.3 computed in double) — bit-exact vs numpy
struct AxTable { float v[NXS]; };
static constexpr AxTable make_ax()
{
    AxTable t{};
    for (int i = 0; i < NXS; ++i) t.v[i] = (float)((double)(i - 20) * 0.3);
    return t;
}
__constant__ AxTable c_ax = make_ax();

// Compile-time conservative non-empty chunk lists per alignment shift a (0..3):
// chunk c listed iff any voxel g = c*128+p+a (p<128, g<GTOT) has r^2 <= 36.01 (double).
// Superset of the true in-sphere chunks -> safe (bounds are verified upper bounds).
struct ChunkLists { short list[4][CHUNKS]; int n[4]; };
static constexpr ChunkLists make_lists()
{
    ChunkLists L{};
    for (int a = 0; a < 4; ++a) {
        int cnt = 0;
        for (int c = 0; c < CHUNKS; ++c) {
            bool ne = false;
            for (int p = c * 128; p < c * 128 + 128 && !ne; ++p) {
                int g = p + a;
                if (g >= GTOT) break;
                int i = g / NX2, j = (g / NXS) % NXS, kk = g % NXS;
                double x = (i - 20) * 0.3, y = (j - 20) * 0.3, z = (kk - 20) * 0.3;
                if (x * x + y * y + z * z <= 36.01) ne = true;
            }
            if (ne) { L.list[a][cnt] = (short)c; ++cnt; }
        }
        L.n[a] = cnt;
    }
    return L;
}
__constant__ ChunkLists c_lists = make_lists();

// Dense sphere mask (exact fp32 semantics), tail words zero
__device__ unsigned int g_S0[NWORDS];

// ---------------------------------------------------------------------------
// Kernel 1: dense sphere mask, numpy-identical fp32 op sequence
// ---------------------------------------------------------------------------
__global__ __launch_bounds__(256) void init_masks_kernel()
{
    __shared__ float ax[NXS];
    if (threadIdx.x < NXS) ax[threadIdx.x] = c_ax.v[threadIdx.x];
    __syncthreads();
    int g = blockIdx.x * 256 + threadIdx.x;    // 270*256 = 69120 = 2160 words
    bool ok = false;
    if (g < GTOT) {
        int i = g / NX2;
        int j = (g / NXS) % NXS;
        int k = g % NXS;
        float x = ax[i], y = ax[j], z = ax[k];
        float s = __fadd_rn(__fadd_rn(__fmul_rn(x, x), __fmul_rn(y, y)), __fmul_rn(z, z));
        ok = (__fsqrt_rn(s) <= 6.0f);
    }
    unsigned int ballot = __ballot_sync(FULLM, ok);
    if ((threadIdx.x & 31) == 0) g_S0[g >> 5] = ballot;
}

// order-preserving float->uint key; 0 = "masked" (below all real keys)
__device__ __forceinline__ unsigned int f2key(float v)
{
    int i = __float_as_int(v);
    return (unsigned int)(i ^ ((i >> 31) | 0x80000000));
}
__device__ __forceinline__ float key2f(unsigned int k)
{
    int i = (k & 0x80000000u) ? (int)(k ^ 0x80000000u) : (int)~k;
    return __int_as_float(i);
}
__device__ __forceinline__ unsigned int sext_bit(unsigned int w, int bitpos)
{
    return (unsigned int)(((int)(w << (31 - bitpos))) >> 31);
}

// ---------------------------------------------------------------------------
// Kernel 2 (fused): 12-warp unmasked float4 chunk scan, then warp-0-only
// verified argmax + lazy Chebyshev NMS (warp-synchronous, no block barriers).
// ---------------------------------------------------------------------------
__global__ __launch_bounds__(NTHR, 4) void peaks_kernel(
    const float* __restrict__ density,   // [512, G]
    const float* __restrict__ grid_xyz,  // [G, 3]
    const float* __restrict__ Rmats,     // [128, 3, 3]
    const float* __restrict__ tpos,      // [128, 3]
    const float* __restrict__ node_mask, // [128]
    float* __restrict__ out)             // 16384 floats
{
    __shared__ unsigned int smask[NWORDS];  // live shifted bits
    __shared__ unsigned int ckey[CHUNKS];   // upper-bound chunk maxima
    __shared__ int          slist[CHUNKS];

    const int pair = blockIdx.x;            // n*4 + c
    const int tid  = threadIdx.x;
    const int lane = tid & 31;
    const int wid  = tid >> 5;
    const int aoff = (-pair) & 3;           // alignment shift (voxels)
    const float4* __restrict__ dens4 =
        (const float4*)(density + (size_t)pair * GTOT + aoff);
    const int nl = c_lists.n[aoff];

    // shifted mask on the fly: S_a[w] = (S0 >> a) across word boundary
    for (int w = tid; w < NWORDS; w += NTHR) {
        unsigned int lo = g_S0[w];
        unsigned int hi = (w + 1 < NWORDS) ? g_S0[w + 1] : 0u;
        smask[w] = __funnelshift_r(lo, hi, aoff);
    }
    for (int c = tid; c < CHUNKS; c += NTHR) ckey[c] = 0u;
    for (int e = tid; e < nl; e += NTHR) slist[e] = c_lists.list[aoff][e];
    __syncthreads();

    // ---- phase A: unmasked per-chunk max over listed chunks (12 warps) ----
    for (int e0 = wid * 4; e0 < nl; e0 += NWARP * 4) {
        int    cc[4];
        float4 ff[4];
        #pragma unroll
        for (int b = 0; b < 4; ++b) {
            int e = min(e0 + b, nl - 1);          // dup-clamped tail
            cc[b] = slist[e];
            ff[b] = __ldg(dens4 + cc[b] * 32 + lane);
        }
        #pragma unroll
        for (int b = 0; b < 4; ++b) {
            float m = fmaxf(fmaxf(ff[b].x, ff[b].y), fmaxf(ff[b].z, ff[b].w));
            unsigned int r = __reduce_max_sync(FULLM, f2key(m));
            if (lane == 0 && e0 + b < nl) ckey[cc[b]] = r;
        }
    }
    __syncthreads();

    if (wid != 0) return;   // warps 1-11 done; no further block barriers

    // ---- phase B: warp-synchronous verified argmax + lazy NMS ----
    float pk_score[KPK];
    int   pk_idx[KPK];
    int   pk_valid[KPK];

    for (int t = 0; t < KPK; ++t) {
        int gi = 0, valid = 0;
        float sc = 0.0f;
        for (;;) {
            // argmax over upper bounds (lowest chunk on ties)
            unsigned int bk = 0;
            int bc = 0x7FFFFFFF;
            for (int c = lane; c < CHUNKS; c += 32) {
                unsigned int k = ckey[c];
                if (k > bk) { bk = k; bc = c; }   // ascending: lowest c per lane
            }
            unsigned int fm = __reduce_max_sync(FULLM, bk);
            int cand = (bk == fm) ? bc : 0x7FFFFFFF;
            int fc = (int)__reduce_min_sync(FULLM, (unsigned int)cand);
            // masked verification of chunk fc
            float4 f = __ldg(dens4 + fc * 32 + lane);
            unsigned int mw = smask[fc * 4 + (lane >> 3)];
            int sh = (lane & 7) * 4;
            unsigned int k0 = f2key(f.x) & sext_bit(mw, sh + 0);
            unsigned int k1 = f2key(f.y) & sext_bit(mw, sh + 1);
            unsigned int k2 = f2key(f.z) & sext_bit(mw, sh + 2);
            unsigned int k3 = f2key(f.w) & sext_bit(mw, sh + 3);
            unsigned int bestk = k0; int besti = 0;
            if (k1 > bestk) { bestk = k1; besti = 1; }
            if (k2 > bestk) { bestk = k2; besti = 2; }
            if (k3 > bestk) { bestk = k3; besti = 3; }
            unsigned int mk = __reduce_max_sync(FULLM, bestk);
            if (mk == fm) {
                // accept: lowest-g argmax within chunk
                int gl = fc * 128 + lane * 4 + besti;
                int cg = (bestk == mk) ? gl : 0x7FFFFFFF;
                int gp = (int)__reduce_min_sync(FULLM, (unsigned int)cg);
                gi = gp + aoff;                  // absolute voxel index
                sc = key2f(fm);
                valid = (sc > VTH) ? 1 : 0;
                break;
            }
            // stale upper bound: decrease-key and retry
            if (lane == 0) ckey[fc] = mk;
            __syncwarp();
        }
        pk_score[t] = sc;
        pk_idx[t]   = gi;
        pk_valid[t] = valid;

        if (t < KPK - 1 && valid) {
            // clear bits in <=7x7x7 Chebyshev cube (shifted coords);
            // ckey stays a valid upper bound; pops self-correct.
            int ci = gi / NX2, cj = (gi / NXS) % NXS, ck = gi % NXS;
            int i0 = max(ci - 3, 0), i1 = min(ci + 3, NXS - 1);
            int j0 = max(cj - 3, 0), j1 = min(cj + 3, NXS - 1);
            int k0c = max(ck - 3, 0), k1c = min(ck + 3, NXS - 1);
            int nj = j1 - j0 + 1;
            int nrows = (i1 - i0 + 1) * nj;
            // rows >=41 bits apart -> never share a 32-bit word -> race-free
            for (int r = lane; r < nrows; r += 32) {
                int i = i0 + r / nj;
                int j = j0 + r % nj;
                int pb = i * NX2 + j * NXS + k0c - aoff;   // shifted position
                int pe = pb + (k1c - k0c);
                int w0 = pb >> 5, w1 = pe >> 5;
                unsigned int b0 = (unsigned int)(pb & 31);
                unsigned int b1 = (unsigned int)(pe & 31);
                unsigned int hi = (b1 == 31u) ? FULLM : ((1u << (b1 + 1)) - 1u);
                if (w0 == w1) {
                    unsigned int msk = hi & ~((1u << b0) - 1u);
                    smask[w0] &= ~msk;
                } else {
                    smask[w0] &= ((1u << b0) - 1u);
                    smask[w1] &= ~hi;
                }
            }
            __syncwarp();
        }
    }

    // ---- outputs (warp 0, lanes 0-3) ----
    // layout: coords_local[6144] | coords_global[6144] | scores[2048] | mask[2048]
    if (lane < KPK) {
        int k = lane;
        int n = pair >> 2;
        float nm = node_mask[n];
        int valid = pk_valid[k];
        float sc = valid ? pk_score[k] : NEGV;
        float x = 0.0f, y = 0.0f, z = 0.0f;
        if (valid) {
            int gi = pk_idx[k];
            x = grid_xyz[3 * gi + 0];
            y = grid_xyz[3 * gi + 1];
            z = grid_xyz[3 * gi + 2];
        }
        int o = (pair * KPK + k) * 3;
        out[o + 0] = x * nm;
        out[o + 1] = y * nm;
        out[o + 2] = z * nm;
        const float* R  = Rmats + n * 9;
        const float* tp = tpos + n * 3;
        float gx = R[0] * x + R[1] * y + R[2] * z + tp[0];
        float gy = R[3] * x + R[4] * y + R[5] * z + tp[1];
        float gz = R[6] * x + R[7] * y + R[8] * z + tp[2];
        out[6144 + o + 0] = gx * nm;
        out[6144 + o + 1] = gy * nm;
        out[6144 + o + 2] = gz * nm;
        out[12288 + pair * KPK + k] = sc * nm;
        out[14336 + pair * KPK + k] = (valid && nm != 0.0f) ? 1.0f : 0.0f;
    }
}

extern "C" void kernel_launch(void* const* d_in, const int* in_sizes, int n_in,
                              void* d_out, int out_size)
{
    // metadata order: density, grid_xyz, sphere_mask, coords_int, Rmats, tpos, node_mask
    const float* density   = (const float*)d_in[0];
    const float* grid_xyz  = (const float*)d_in[1];
    const float* Rmats     = (const float*)d_in[4];
    const float* tpos      = (const float*)d_in[5];
    const float* node_mask = (const float*)d_in[6];
    float* out = (float*)d_out;

    init_masks_kernel<<<270, 256>>>();
    peaks_kernel<<<NPAIR, NTHR>>>(density, grid_xyz, Rmats, tpos, node_mask, out);
}